// round 17
// baseline (speedup 1.0000x reference)
#include <cuda_runtime.h>
#include <cuda_fp16.h>
#include <math.h>
#include <stdint.h>

#define C 128
#define NE_MAX 800000
#define NN_MAX 50000
#define BN_EPS 1e-5f

// ---------------- scratch (device globals; no runtime alloc) ----------------
__device__ float g_h[(size_t)NE_MAX * C / 2]; // edge MLP pre-BN output (fp16, SORTED by col)
__device__ float g_xa[(size_t)NN_MAX * C];    // x @ w1a^T
__device__ float g_agg[(size_t)NN_MAX * C];   // per-node mean numerator
__device__ float g_pre[(size_t)NN_MAX * C];   // node MLP pre-BN output
__device__ int   g_hist[NN_MAX];              // edge count per node
__device__ int   g_off[NN_MAX];               // CSR start offsets
__device__ int   g_cur[NN_MAX];               // permute cursors
__device__ int   g_bsum[256];                 // scan block sums
__device__ int   g_pos[NE_MAX];               // edge -> sorted slot
__device__ float g_s1[C], g_q1[C], g_s2[C], g_q2[C];
__device__ float g_a1[C], g_c1[C], g_a2[C], g_c2[C];
// fp16 weight blobs in smem-swizzled [n][k] layout: 0=w1a 1=w1b 2=w2a 3=w2b
__device__ __align__(16) uint16_t g_wblob[4][128 * 128];

// ---------------- helpers ----------------
__device__ __forceinline__ uint32_t smem_u32(const void* p) {
    return (uint32_t)__cvta_generic_to_shared(p);
}
__device__ __forceinline__ void ldsm4(uint32_t* r, uint32_t addr) {
    asm volatile("ldmatrix.sync.aligned.m8n8.x4.shared.b16 {%0,%1,%2,%3}, [%4];"
                 : "=r"(r[0]), "=r"(r[1]), "=r"(r[2]), "=r"(r[3]) : "r"(addr));
}
__device__ __forceinline__ void mma16816(float* c, const uint32_t* a, const uint32_t* b) {
    asm volatile(
        "mma.sync.aligned.m16n8k16.row.col.f32.f16.f16.f32 "
        "{%0,%1,%2,%3}, {%4,%5,%6,%7}, {%8,%9}, {%0,%1,%2,%3};"
        : "+f"(c[0]), "+f"(c[1]), "+f"(c[2]), "+f"(c[3])
        : "r"(a[0]), "r"(a[1]), "r"(a[2]), "r"(a[3]), "r"(b[0]), "r"(b[1]));
}
__device__ __forceinline__ void cpasync16(uint32_t dst, const void* src) {
    asm volatile("cp.async.cg.shared.global [%0], [%1], 16;"
                 :: "r"(dst), "l"(src) : "memory");
}
__device__ __forceinline__ void cp_commit() {
    asm volatile("cp.async.commit_group;" ::: "memory");
}
__device__ __forceinline__ void cp_wait0() {
    asm volatile("cp.async.wait_group 0;" ::: "memory");
}
__device__ __forceinline__ unsigned pack2(float a, float b) {
    __half2 p = __floats2half2_rn(a, b);
    return *reinterpret_cast<unsigned*>(&p);
}
__device__ __forceinline__ float eluf(float v) { return v > 0.f ? v : expm1f(v); }
__device__ __forceinline__ uint32_t swz(int row, int kg) {
    return ((uint32_t)row << 8) + (((uint32_t)(kg ^ (row & 7))) << 4);
}

// ---------------- small kernels ----------------
__global__ void zero_kernel() {
    int g = blockIdx.x * 256 + threadIdx.x;
    if (g < NN_MAX) g_hist[g] = 0;
    if (g < C) { g_s1[g] = 0.f; g_q1[g] = 0.f; g_s2[g] = 0.f; g_q2[g] = 0.f; }
}

__global__ void prep_w(const float* __restrict__ w1, const float* __restrict__ w2) {
    int t = blockIdx.x * 256 + threadIdx.x;   // 0..2047
    if (t >= 2048) return;
    int n = t >> 4;
    int kg = t & 15;
    uint32_t sw = swz(n, kg);
#pragma unroll
    for (int m = 0; m < 4; m++) {
        const float* src = (m < 2 ? w1 : w2) + (size_t)n * 256 + (m & 1) * 128 + kg * 8;
        uint4 u;
        u.x = pack2(src[0], src[1]);
        u.y = pack2(src[2], src[3]);
        u.z = pack2(src[4], src[5]);
        u.w = pack2(src[6], src[7]);
        *(uint4*)((char*)g_wblob[m] + sw) = u;
    }
}

// ---------------- counting sort of edges by destination ----------------
__global__ void hist_kernel(const int* __restrict__ col, int E) {
    int e = blockIdx.x * 256 + threadIdx.x;
    if (e < E) atomicAdd(&g_hist[col[e]], 1);
}

__global__ void scan1_kernel(int n) {
    __shared__ int wsum[8];
    int i = blockIdx.x * 256 + threadIdx.x;
    int lane = threadIdx.x & 31, w = threadIdx.x >> 5;
    int v = (i < n) ? g_hist[i] : 0;
    int x = v;
#pragma unroll
    for (int o = 1; o < 32; o <<= 1) {
        int y = __shfl_up_sync(~0u, x, o); if (lane >= o) x += y;
    }
    if (lane == 31) wsum[w] = x;
    __syncthreads();
    if (w == 0) {
        int s = (lane < 8) ? wsum[lane] : 0;
#pragma unroll
        for (int o = 1; o < 8; o <<= 1) {
            int y = __shfl_up_sync(~0u, s, o); if (lane >= o) s += y;
        }
        if (lane < 8) wsum[lane] = s;
    }
    __syncthreads();
    int base = (w > 0) ? wsum[w - 1] : 0;
    int incl = x + base;
    if (i < n) g_off[i] = incl - v;
    if (threadIdx.x == 255) g_bsum[blockIdx.x] = incl;
}

__global__ void scan2_kernel(int nb) {
    __shared__ int wsum[8];
    int t = threadIdx.x, lane = t & 31, w = t >> 5;
    int v = (t < nb) ? g_bsum[t] : 0;
    int x = v;
#pragma unroll
    for (int o = 1; o < 32; o <<= 1) {
        int y = __shfl_up_sync(~0u, x, o); if (lane >= o) x += y;
    }
    if (lane == 31) wsum[w] = x;
    __syncthreads();
    if (w == 0) {
        int s = (lane < 8) ? wsum[lane] : 0;
#pragma unroll
        for (int o = 1; o < 8; o <<= 1) {
            int y = __shfl_up_sync(~0u, s, o); if (lane >= o) s += y;
        }
        if (lane < 8) wsum[lane] = s;
    }
    __syncthreads();
    int base = (w > 0) ? wsum[w - 1] : 0;
    if (t < nb) g_bsum[t] = x + base - v;
}

__global__ void scan3_kernel(int n) {
    int i = blockIdx.x * 256 + threadIdx.x;
    if (i < n) {
        int o = g_off[i] + g_bsum[blockIdx.x];
        g_off[i] = o;
        g_cur[i] = o;
    }
}

__global__ void permute_kernel(const int* __restrict__ col, int E) {
    int e = blockIdx.x * 256 + threadIdx.x;
    if (e < E) g_pos[e] = atomicAdd(&g_cur[col[e]], 1);
}

// ---------------- persistent mma.sync GEMM (BM=64, fp16, cp.async pipelined) ----------------
// MODE 0: g_xa  = x @ w1a^T                               (fp32 out)
// MODE 1: g_h(fp16, sorted rows) = ea @ w1b^T + g_xa[row[m]] + b1  (+ BN1 stats)
// MODE 2: g_pre = x @ w2a^T + (agg/cnt) @ w2b^T + b2      (+ BN2 stats; K=256, LDG path)
// smem: BH 0(32K) / RAW 32K(32K) / A0 64K(16K) / A1 80K(16K) -> 96 KB, 2 CTAs/SM
template <int MODE>
__global__ void __launch_bounds__(256, 2) mm_kernel(
    const float* __restrict__ A, const float* __restrict__ bias,
    const int* __restrict__ rowidx, int M)
{
    extern __shared__ __align__(16) char sm[];
    constexpr int BH = 0, RAW = 32768, A0 = 65536;
    constexpr bool STATS = (MODE == 1) || (MODE == 2);

    const int tid = threadIdx.x;
    const int lane = tid & 31, wid = tid >> 5;
    const int wm = wid >> 2;          // 0..1 : 32-row group
    const int wn = wid & 3;           // 0..3 : 32-col group

    float* Sg = (MODE == 1) ? g_s1 : g_s2;
    float* Qg = (MODE == 1) ? g_q1 : g_q2;

    // ---- stage B (single-k modes: once) ----
    if (MODE != 2) {
        const uint4* bh = (const uint4*)g_wblob[(MODE == 0) ? 0 : 1];
        for (int i = tid; i < 2048; i += 256)
            ((uint4*)(sm + BH))[i] = bh[i];
    }

    const uint32_t sb = smem_u32(sm);
    const uint32_t rx = lane & 7;
    const uint32_t rbA = (uint32_t)(wm * 32 + (lane & 15)) << 8;
    const uint32_t kgoA = lane >> 4;
    uint32_t rbB[2];
#pragma unroll
    for (int nf2 = 0; nf2 < 2; nf2++)
        rbB[nf2] = (uint32_t)(wn * 32 + nf2 * 16 + ((lane >> 4) << 3) + (lane & 7)) << 8;
    const uint32_t kgoB = (lane >> 3) & 1;

    const int np = (lane & 3) * 2;
    float s0[4], s1[4], q0[4], q1[4];
#pragma unroll
    for (int nf = 0; nf < 4; nf++) { s0[nf] = s1[nf] = q0[nf] = q1[nf] = 0.f; }

    // ---- lambdas ----
    auto cpA = [&](int t) {                       // async raw f32 64x128 tile -> RAW
#pragma unroll
        for (int it = 0; it < 8; it++) {
            int gi = it * 256 + tid;              // 0..2047 16B chunks
            int r = gi >> 5, q = gi & 31;
            int m = t * 64 + r; if (m >= M) m = M - 1;
            cpasync16(sb + RAW + gi * 16, A + (size_t)m * C + q * 4);
        }
        cp_commit();
    };
    auto convA = [&](uint32_t abase) {            // RAW f32 -> fp16 swizzled
#pragma unroll
        for (int it = 0; it < 4; it++) {
            int u = it * 256 + tid;               // 0..1023 8-float units
            int r = u >> 4, kg = u & 15;
            const float4* rp = (const float4*)(sm + RAW + r * 512 + kg * 32);
            float4 va = rp[0], vb = rp[1];
            uint4 u4;
            u4.x = pack2(va.x, va.y); u4.y = pack2(va.z, va.w);
            u4.z = pack2(vb.x, vb.y); u4.w = pack2(vb.z, vb.w);
            *(uint4*)(sm + abase + swz(r, kg)) = u4;
        }
    };
    auto mainloop = [&](uint32_t abase, float acc[2][4][4]) {
#pragma unroll
        for (int ks = 0; ks < 8; ks++) {
            uint32_t offA = ((2 * ks + kgoA) ^ rx) << 4;
            uint32_t offB = ((2 * ks + kgoB) ^ rx) << 4;
            uint32_t ah[2][4];
            ldsm4(ah[0], sb + abase + rbA + offA);
            ldsm4(ah[1], sb + abase + rbA + (16 << 8) + offA);
#pragma unroll
            for (int nf2 = 0; nf2 < 2; nf2++) {
                uint32_t bh[4];
                ldsm4(bh, sb + BH + rbB[nf2] + offB);
#pragma unroll
                for (int j = 0; j < 2; j++) {
                    const uint32_t* fh = &bh[j * 2];
                    mma16816(acc[0][nf2 * 2 + j], ah[0], fh);
                    mma16816(acc[1][nf2 * 2 + j], ah[1], fh);
                }
            }
        }
    };
    auto epilogue = [&](int mbase, float acc[2][4][4]) {
        const int g = lane >> 2;
#pragma unroll
        for (int mi = 0; mi < 2; mi++) {
#pragma unroll
            for (int h = 0; h < 2; h++) {
                int r = wm * 32 + mi * 16 + h * 8 + g;
                int m = mbase + r;
                bool valid = (m < M);
                const float* xr = nullptr;
                float* orow = nullptr;
                if (valid) {
                    if (MODE == 0) orow = g_xa + (size_t)m * C;
                    else if (MODE == 2) orow = g_pre + (size_t)m * C;
                    else {
                        xr = g_xa + (size_t)__ldg(&rowidx[m]) * C;
                        orow = (float*)((__half*)g_h + (size_t)__ldg(&g_pos[m]) * C);
                    }
                }
#pragma unroll
                for (int nf = 0; nf < 4; nf++) {
                    int col = wn * 32 + nf * 8 + np;
                    float o0 = acc[mi][nf][h * 2 + 0];
                    float o1 = acc[mi][nf][h * 2 + 1];
                    if (MODE != 0 && valid) { o0 += bias[col]; o1 += bias[col + 1]; }
                    if (MODE == 1 && valid) {
                        float2 xv = *(const float2*)(xr + col);
                        o0 += xv.x; o1 += xv.y;
                    }
                    if (valid) {
                        if (MODE == 1) {
                            *(__half2*)((__half*)orow + col) = __floats2half2_rn(o0, o1);
                        } else {
                            *(float2*)(orow + col) = make_float2(o0, o1);
                        }
                        if (STATS) {
                            s0[nf] += o0; q0[nf] += o0 * o0;
                            s1[nf] += o1; q1[nf] += o1 * o1;
                        }
                    }
                }
            }
        }
    };

    const int tiles = (M + 63) >> 6;

    if (MODE != 2) {
        // ---- cp.async pipelined persistent loop ----
        int t = blockIdx.x;
        if (t >= tiles) return;
        cpA(t);
        cp_wait0();
        __syncthreads();          // RAW ready + B staged
        convA(A0);
        __syncthreads();          // A0 ready
        int buf = 0;
        while (true) {
            int tn = t + gridDim.x;
            if (tn < tiles) cpA(tn);    // overlaps mainloop+epilogue

            float acc[2][4][4];
#pragma unroll
            for (int mi = 0; mi < 2; mi++)
#pragma unroll
                for (int nf = 0; nf < 4; nf++)
#pragma unroll
                    for (int cc = 0; cc < 4; cc++) acc[mi][nf][cc] = 0.f;

            mainloop(A0 + buf * 16384, acc);
            epilogue(t * 64, acc);

            if (tn >= tiles) break;
            cp_wait0();
            __syncthreads();      // RAW(tn) landed; everyone past convA reads
            convA(A0 + (buf ^ 1) * 16384);
            __syncthreads();
            buf ^= 1; t = tn;
        }
    } else {
        // ---- fused node GEMM (K=256), LDG staging path ----
        for (int t = blockIdx.x; t < tiles; t += gridDim.x) {
            const int mbase = t * 64;
            float acc[2][4][4];
#pragma unroll
            for (int mi = 0; mi < 2; mi++)
#pragma unroll
                for (int nf = 0; nf < 4; nf++)
#pragma unroll
                    for (int cc = 0; cc < 4; cc++) acc[mi][nf][cc] = 0.f;
#pragma unroll
            for (int kt = 0; kt < 2; kt++) {
                __syncthreads();
                // stage B for this k-tile
                const uint4* bh = (const uint4*)g_wblob[2 + kt];
                for (int i = tid; i < 2048; i += 256)
                    ((uint4*)(sm + BH))[i] = bh[i];
                // stage A (LDG) into A0
                const float* Ap = (kt == 1) ? (const float*)g_agg : A;
#pragma unroll
                for (int it = 0; it < 4; it++) {
                    int u = it * 256 + tid;
                    int r = u >> 4, kg = u & 15;
                    int m = mbase + r; if (m >= M) m = M - 1;
                    const float* src = Ap + (size_t)m * C + kg * 8;
                    float4 va = *(const float4*)src;
                    float4 vb = *(const float4*)(src + 4);
                    if (kt == 1) {
                        float s = __frcp_rn(fmaxf((float)g_hist[m], 1.f));
                        va.x *= s; va.y *= s; va.z *= s; va.w *= s;
                        vb.x *= s; vb.y *= s; vb.z *= s; vb.w *= s;
                    }
                    uint4 u4;
                    u4.x = pack2(va.x, va.y); u4.y = pack2(va.z, va.w);
                    u4.z = pack2(vb.x, vb.y); u4.w = pack2(vb.z, vb.w);
                    *(uint4*)(sm + A0 + swz(r, kg)) = u4;
                }
                __syncthreads();
                mainloop(A0, acc);
            }
            epilogue(mbase, acc);
        }
    }

    // ---- flush BN stats once per warp ----
    if (STATS) {
#pragma unroll
        for (int nf = 0; nf < 4; nf++) {
#pragma unroll
            for (int off = 4; off <= 16; off <<= 1) {
                s0[nf] += __shfl_xor_sync(0xffffffffu, s0[nf], off);
                s1[nf] += __shfl_xor_sync(0xffffffffu, s1[nf], off);
                q0[nf] += __shfl_xor_sync(0xffffffffu, q0[nf], off);
                q1[nf] += __shfl_xor_sync(0xffffffffu, q1[nf], off);
            }
        }
        if (lane < 4) {
#pragma unroll
            for (int nf = 0; nf < 4; nf++) {
                int col = wn * 32 + nf * 8 + lane * 2;
                atomicAdd(&Sg[col], s0[nf]); atomicAdd(&Sg[col + 1], s1[nf]);
                atomicAdd(&Qg[col], q0[nf]); atomicAdd(&Qg[col + 1], q1[nf]);
            }
        }
    }
}

// ---------------- BN coefficient finalize ----------------
__global__ void finalize_kernel(int sel, const float* __restrict__ bnw,
                                const float* __restrict__ bnb, float minv) {
    int j = threadIdx.x;
    float s  = sel ? g_s2[j] : g_s1[j];
    float q  = sel ? g_q2[j] : g_q1[j];
    float mu = s * minv;
    float var = q * minv - mu * mu;
    float r = rsqrtf(var + BN_EPS);
    float a = r * bnw[j];
    float c = bnb[j] - mu * a;
    if (sel) { g_a2[j] = a; g_c2[j] = c; }
    else     { g_a1[j] = a; g_c1[j] = c; }
}

// ---------------- BN1 + ELU + contiguous segment-sum over sorted fp16 h ----------------
__global__ void __launch_bounds__(256) segsum_kernel(int n) {
    int wg = (blockIdx.x * 256 + threadIdx.x) >> 5;
    int lane = threadIdx.x & 31;
    if (wg >= n) return;
    int s = g_off[wg];
    int cnt = g_hist[wg];
    int cq = lane * 4;
    float4 a = *(const float4*)(g_a1 + cq);
    float4 c = *(const float4*)(g_c1 + cq);
    const __half* hp = (const __half*)g_h;
    float4 acc = {0.f, 0.f, 0.f, 0.f};
    auto accum = [&](uint2 raw) {
        float2 f0 = __half22float2(*(__half2*)&raw.x);
        float2 f1 = __half22float2(*(__half2*)&raw.y);
        acc.x += eluf(fmaf(f0.x, a.x, c.x));
        acc.y += eluf(fmaf(f0.y, a.y, c.y));
        acc.z += eluf(fmaf(f1.x, a.z, c.z));
        acc.w += eluf(fmaf(f1.y, a.w, c.w));
    };
    const uint2* base = (const uint2*)(hp + (size_t)s * C) + lane;
    int j = 0;
    for (; j + 4 <= cnt; j += 4) {
        uint2 r0 = __ldcs(base + (size_t)(j + 0) * 32);
        uint2 r1 = __ldcs(base + (size_t)(j + 1) * 32);
        uint2 r2 = __ldcs(base + (size_t)(j + 2) * 32);
        uint2 r3 = __ldcs(base + (size_t)(j + 3) * 32);
        accum(r0); accum(r1); accum(r2); accum(r3);
    }
    for (; j < cnt; j++) {
        uint2 r = __ldcs(base + (size_t)j * 32);
        accum(r);
    }
    *(float4*)(g_agg + (size_t)wg * C + cq) = acc;
}

// ---------------- BN2 + ELU -> output ----------------
__global__ void final_kernel(float* __restrict__ out, int n) {
    int g = blockIdx.x * 256 + threadIdx.x;
    if (g >= n * 32) return;
    int cq = (g & 31) * 4;
    float4 v = *(const float4*)(g_pre + (size_t)g * 4);
    float4 a = *(const float4*)(g_a2 + cq);
    float4 c = *(const float4*)(g_c2 + cq);
    float4 o;
    o.x = eluf(fmaf(v.x, a.x, c.x));
    o.y = eluf(fmaf(v.y, a.y, c.y));
    o.z = eluf(fmaf(v.z, a.z, c.z));
    o.w = eluf(fmaf(v.w, a.w, c.w));
    *(float4*)(out + (size_t)g * 4) = o;
}

// ---------------- launch ----------------
extern "C" void kernel_launch(void* const* d_in, const int* in_sizes, int n_in,
                              void* d_out, int out_size) {
    const float* x    = (const float*)d_in[0];
    const int*   ei   = (const int*)d_in[1];
    const float* ea   = (const float*)d_in[2];
    const float* w1   = (const float*)d_in[5];
    const float* b1   = (const float*)d_in[6];
    const float* bn1w = (const float*)d_in[7];
    const float* bn1b = (const float*)d_in[8];
    const float* w2   = (const float*)d_in[9];
    const float* b2   = (const float*)d_in[10];
    const float* bn2w = (const float*)d_in[11];
    const float* bn2b = (const float*)d_in[12];
    float* out = (float*)d_out;

    int n = in_sizes[0] / C;           // 50000
    int E = in_sizes[2] / C;           // 800000
    const int* row = ei;
    const int* col = ei + E;

    const int SMEM = 98304;            // 96 KB -> 2 CTAs/SM
    cudaFuncSetAttribute(mm_kernel<0>, cudaFuncAttributeMaxDynamicSharedMemorySize, SMEM);
    cudaFuncSetAttribute(mm_kernel<1>, cudaFuncAttributeMaxDynamicSharedMemorySize, SMEM);
    cudaFuncSetAttribute(mm_kernel<2>, cudaFuncAttributeMaxDynamicSharedMemorySize, SMEM);

    int nb = (n + 255) / 256;          // scan blocks (<=256 required)

    const int GRID = 296;              // 2 persistent CTAs per SM
    int ngrid = min(GRID, (n + 63) / 64);
    int egrid = min(GRID, (E + 63) / 64);

    zero_kernel<<<(NN_MAX + 255) / 256, 256>>>();
    prep_w<<<8, 256>>>(w1, w2);

    // counting sort (must precede mm<1>: h rows are written in sorted order)
    hist_kernel<<<(E + 255) / 256, 256>>>(col, E);
    scan1_kernel<<<nb, 256>>>(n);
    scan2_kernel<<<1, 256>>>(nb);
    scan3_kernel<<<nb, 256>>>(n);
    permute_kernel<<<(E + 255) / 256, 256>>>(col, E);

    // xa = x @ w1a^T
    mm_kernel<0><<<ngrid, 256, SMEM>>>(x, nullptr, nullptr, n);
    // h(sorted) = ea @ w1b^T + xa[row] + b1  (stats fused)
    mm_kernel<1><<<egrid, 256, SMEM>>>(ea, b1, row, E);
    finalize_kernel<<<1, C>>>(0, bn1w, bn1b, 1.f / (float)E);

    // agg = segment_sum(elu(bn1(h)))  (contiguous CSR, no atomics)
    segsum_kernel<<<(n * 32 + 255) / 256, 256>>>(n);

    // pre = x @ w2a^T + (agg/cnt) @ w2b^T + b2   (fused K=256, stats fused)
    mm_kernel<2><<<ngrid, 256, SMEM>>>(x, b2, nullptr, n);
    finalize_kernel<<<1, C>>>(1, bn2w, bn2b, 1.f / (float)n);

    final_kernel<<<(n * 32 + 255) / 256, 256>>>(out, n);
}